// round 2
// baseline (speedup 1.0000x reference)
#include <cuda_runtime.h>
#include <cuda_bf16.h>
#include <cstdint>
#include <math.h>

// ----------------------------------------------------------------------------
// Problem constants
// ----------------------------------------------------------------------------
#define N_BATCH   4096
#define D_EMB     512
#define TWO_N     8192
#define LAMBDA    0.5f
#define TILE      128
#define NTILE     (TWO_N / TILE)                 // 64
#define NBLK_TRI  (NTILE * (NTILE + 1) / 2)      // 2080 lower-triangle tiles
#define KCHUNK    64                             // bf16 per K-chunk (128B rows)
#define NCHUNK    (D_EMB / KCHUNK)               // 8
#define STAGE_BYTES (TILE * 128)                 // 16384 per matrix per stage
#define SMEM_DYN    (2 * 2 * STAGE_BYTES)        // 65536: 2 stages x (A,B)

// ----------------------------------------------------------------------------
// Device scratch (static — no allocations allowed)
// ----------------------------------------------------------------------------
__device__ __nv_bfloat16 g_reps[(size_t)TWO_N * D_EMB];   // 8 MB, L2-resident
__device__ float g_neg_part[NBLK_TRI];
__device__ float g_pos_part[N_BATCH];

// ----------------------------------------------------------------------------
// Helpers (arch-neutral PTX only: ldmatrix / mma.sync / cp.async)
// ----------------------------------------------------------------------------
__device__ __forceinline__ uint32_t smem_to_u32(const void* p) {
    uint32_t a;
    asm("{ .reg .u64 t; cvta.to.shared.u64 t, %1; cvt.u32.u64 %0, t; }" : "=r"(a) : "l"(p));
    return a;
}

__device__ __forceinline__ void ldsm_x4(uint32_t& r0, uint32_t& r1, uint32_t& r2,
                                        uint32_t& r3, uint32_t addr) {
    asm volatile("ldmatrix.sync.aligned.m8n8.x4.shared.b16 {%0,%1,%2,%3}, [%4];"
                 : "=r"(r0), "=r"(r1), "=r"(r2), "=r"(r3) : "r"(addr));
}

__device__ __forceinline__ void mma_16816(float* c, const uint32_t* a, uint32_t b0,
                                          uint32_t b1) {
    asm volatile(
        "mma.sync.aligned.m16n8k16.row.col.f32.bf16.bf16.f32 "
        "{%0,%1,%2,%3}, {%4,%5,%6,%7}, {%8,%9}, {%0,%1,%2,%3};"
        : "+f"(c[0]), "+f"(c[1]), "+f"(c[2]), "+f"(c[3])
        : "r"(a[0]), "r"(a[1]), "r"(a[2]), "r"(a[3]), "r"(b0), "r"(b1));
}

#define CP_ASYNC16(dst, src) \
    asm volatile("cp.async.cg.shared.global [%0], [%1], 16;" :: "r"(dst), "l"(src))
#define CP_COMMIT() asm volatile("cp.async.commit_group;" ::: "memory")
#define CP_WAIT(n)  asm volatile("cp.async.wait_group %0;" :: "n"(n) : "memory")

// SW128-style swizzle on 128B rows: 16B segment index XOR (row & 7) -> conflict-free
__device__ __forceinline__ uint32_t sw_off(int row, int seg) {
    return (uint32_t)(row * 128 + ((seg ^ (row & 7)) << 4));
}

// softplus(x) = x/2 + ln2 + v/2 - v^2/12 + v^3/45 - 17v^4/2520 + 31v^5/14175, v=(x/2)^2
// err < 1e-6 for |x| <= 1.2 (sims are ~N(0,1/512): |x| <~ 0.9 incl. lambda shift)
__device__ __forceinline__ float softplus_poly(float x) {
    float v = 0.25f * x * x;
    float p = fmaf(v, 2.1869489e-3f, -6.7460317e-3f);
    p = fmaf(v, p, 2.2222222e-2f);
    p = fmaf(v, p, -8.3333333e-2f);
    p = fmaf(v, p, 0.5f);
    p = fmaf(v, p, 0.69314718056f);
    return fmaf(0.5f, x, p);
}

// ----------------------------------------------------------------------------
// Kernel 1: L2-normalize rows -> bf16 reps[8192][512]
// ----------------------------------------------------------------------------
__global__ __launch_bounds__(128) void norm_kernel(const float* __restrict__ ei,
                                                   const float* __restrict__ ej) {
    int row = blockIdx.x;
    const float* src = (row < N_BATCH) ? (ei + (size_t)row * D_EMB)
                                       : (ej + (size_t)(row - N_BATCH) * D_EMB);
    int tid = threadIdx.x;
    float v[4];
    float ss = 0.f;
#pragma unroll
    for (int k = 0; k < 4; k++) {
        v[k] = src[tid + k * 128];
        ss = fmaf(v[k], v[k], ss);
    }
#pragma unroll
    for (int o = 16; o > 0; o >>= 1) ss += __shfl_down_sync(0xffffffffu, ss, o);
    __shared__ float sred[4];
    if ((tid & 31) == 0) sred[tid >> 5] = ss;
    __syncthreads();
    float inv = rsqrtf(sred[0] + sred[1] + sred[2] + sred[3]);
    __nv_bfloat16* dst = g_reps + (size_t)row * D_EMB;
#pragma unroll
    for (int k = 0; k < 4; k++) dst[tid + k * 128] = __float2bfloat16(v[k] * inv);
}

// ----------------------------------------------------------------------------
// Kernel 2: positives  g_pos_part[k] = softplus(lambda - z_i[k] . z_j[k])
// ----------------------------------------------------------------------------
__global__ __launch_bounds__(128) void pos_kernel() {
    int k = blockIdx.x;
    int tid = threadIdx.x;
    const __nv_bfloat16* a = g_reps + (size_t)k * D_EMB;
    const __nv_bfloat16* b = g_reps + (size_t)(k + N_BATCH) * D_EMB;
    float dot = 0.f;
#pragma unroll
    for (int i = 0; i < 4; i++) {
        int idx = tid + i * 128;
        dot = fmaf(__bfloat162float(a[idx]), __bfloat162float(b[idx]), dot);
    }
#pragma unroll
    for (int o = 16; o > 0; o >>= 1) dot += __shfl_down_sync(0xffffffffu, dot, o);
    __shared__ float sred[4];
    if ((tid & 31) == 0) sred[tid >> 5] = dot;
    __syncthreads();
    if (tid == 0) {
        float s = sred[0] + sred[1] + sred[2] + sred[3];
        g_pos_part[k] = log1pf(expf(LAMBDA - s));
    }
}

// ----------------------------------------------------------------------------
// Kernel 3: triangle-tiled HMMA GEMM with fused softplus-sum epilogue.
// One 256-thread CTA per lower-triangle 128x128 tile of sim = R R^T.
// 8 warps (4x2): warp computes a 32x64 strip via m16n8k16 bf16 mma.sync.
// 2-stage cp.async double buffer over K (chunks of 64).
// ----------------------------------------------------------------------------
__global__ __launch_bounds__(256) void gemm_kernel() {
    extern __shared__ __align__(1024) uint8_t smem[];  // [stage][A|B][128][128B]
    __shared__ float s_red[8];

    // decode linear tile index -> (I, J) with I >= J
    int t = blockIdx.x;
    int I = (int)((sqrt(8.0 * (double)t + 1.0) - 1.0) * 0.5);
    while ((I + 1) * (I + 2) / 2 <= t) I++;
    while (I * (I + 1) / 2 > t) I--;
    int J = t - I * (I + 1) / 2;

    int tid = threadIdx.x, wid = tid >> 5, lane = tid & 31;
    int wm = wid & 3;        // row strip: wm*32
    int wn = wid >> 2;       // col strip: wn*64
    uint32_t sbase = smem_to_u32(smem);

    const __nv_bfloat16* repA = g_reps + (size_t)(I * TILE) * D_EMB;
    const __nv_bfloat16* repB = g_reps + (size_t)(J * TILE) * D_EMB;

    // cp.async mapping: thread t loads 4 rows (rowbase + 32*i) of one 16B segment
    const int seg = tid & 7;        // 16B segment within 128B row
    const int rowbase = tid >> 3;   // 0..31

    auto load_stage = [&](int c, int stage) {
        uint32_t sA = sbase + stage * (2 * STAGE_BYTES);
        uint32_t sB = sA + STAGE_BYTES;
        const __nv_bfloat16* gA = repA + c * KCHUNK + seg * 8;
        const __nv_bfloat16* gB = repB + c * KCHUNK + seg * 8;
#pragma unroll
        for (int i = 0; i < 4; i++) {
            int row = rowbase + i * 32;
            uint32_t o = sw_off(row, seg);
            CP_ASYNC16(sA + o, gA + (size_t)row * D_EMB);
            CP_ASYNC16(sB + o, gB + (size_t)row * D_EMB);
        }
    };

    float acc[2][8][4];
#pragma unroll
    for (int mi = 0; mi < 2; mi++)
#pragma unroll
        for (int ni = 0; ni < 8; ni++)
#pragma unroll
            for (int p = 0; p < 4; p++) acc[mi][ni][p] = 0.f;

    // ldmatrix address rows (within tile) for this lane
    const int lrow = lane & 15;      // row within 16-row group
    const int lhalf = lane >> 4;     // which 16B k-half

    load_stage(0, 0);
    CP_COMMIT();

    for (int c = 0; c < NCHUNK; c++) {
        if (c + 1 < NCHUNK) {
            load_stage(c + 1, (c + 1) & 1);
            CP_COMMIT();
            CP_WAIT(1);
        } else {
            CP_WAIT(0);
        }
        __syncthreads();

        uint32_t sA = sbase + (c & 1) * (2 * STAGE_BYTES);
        uint32_t sB = sA + STAGE_BYTES;

#pragma unroll
        for (int k16 = 0; k16 < 4; k16++) {
            int kseg = k16 * 2 + lhalf;
            // A fragments: 2 m-tiles of 16 rows
            uint32_t a0[4], a1[4];
            {
                int r = wm * 32 + lrow;
                ldsm_x4(a0[0], a0[1], a0[2], a0[3], sA + sw_off(r, kseg));
                r += 16;
                ldsm_x4(a1[0], a1[1], a1[2], a1[3], sA + sw_off(r, kseg));
            }
            // B fragments: 4 groups of 16 n-rows
            uint32_t br[4][4];
#pragma unroll
            for (int ng = 0; ng < 4; ng++) {
                int r = wn * 64 + ng * 16 + lrow;
                ldsm_x4(br[ng][0], br[ng][1], br[ng][2], br[ng][3],
                        sB + sw_off(r, kseg));
            }
#pragma unroll
            for (int ni = 0; ni < 8; ni++) {
                int ng = ni >> 1, hi = ni & 1;
                mma_16816(acc[0][ni], a0, br[ng][hi], br[ng][hi + 2]);
                mma_16816(acc[1][ni], a1, br[ng][hi], br[ng][hi + 2]);
            }
        }
        __syncthreads();
    }

    // Fused epilogue: softplus(sim - lambda), mask true diagonal, x2 off-diag tiles
    bool diag = (I == J);
    int row0 = I * TILE + wm * 32 + (lane >> 2);
    int col0 = J * TILE + wn * 64 + (lane & 3) * 2;
    float asum = 0.f;
#pragma unroll
    for (int mi = 0; mi < 2; mi++) {
#pragma unroll
        for (int ni = 0; ni < 8; ni++) {
#pragma unroll
            for (int p = 0; p < 4; p++) {
                int gr = row0 + mi * 16 + ((p >> 1) << 3);
                int gc = col0 + ni * 8 + (p & 1);
                float g = softplus_poly(acc[mi][ni][p] - LAMBDA);
                if (!diag || gr != gc) asum += g;
            }
        }
    }
    if (!diag) asum *= 2.f;

#pragma unroll
    for (int o = 16; o > 0; o >>= 1) asum += __shfl_down_sync(0xffffffffu, asum, o);
    if (lane == 0) s_red[wid] = asum;
    __syncthreads();
    if (tid == 0) {
        float s = 0.f;
#pragma unroll
        for (int w = 0; w < 8; w++) s += s_red[w];
        g_neg_part[t] = s;
    }
}

// ----------------------------------------------------------------------------
// Kernel 4: deterministic final reduction
// ----------------------------------------------------------------------------
__global__ __launch_bounds__(256) void fin_kernel(float* __restrict__ out) {
    int tid = threadIdx.x;
    double sn = 0.0, sp = 0.0;
    for (int i = tid; i < NBLK_TRI; i += 256) sn += (double)g_neg_part[i];
    for (int i = tid; i < N_BATCH; i += 256) sp += (double)g_pos_part[i];
#pragma unroll
    for (int o = 16; o > 0; o >>= 1) {
        sn += __shfl_down_sync(0xffffffffu, sn, o);
        sp += __shfl_down_sync(0xffffffffu, sp, o);
    }
    __shared__ double shn[8], shp[8];
    if ((tid & 31) == 0) { shn[tid >> 5] = sn; shp[tid >> 5] = sp; }
    __syncthreads();
    if (tid == 0) {
        double tn = 0.0, tp = 0.0;
#pragma unroll
        for (int i = 0; i < 8; i++) { tn += shn[i]; tp += shp[i]; }
        // positives_sum = 2*P/(2n) = P/4096 ; negatives_sum = Sneg/(12n) = Sneg/49152
        out[0] = (float)(tp / 4096.0 + tn / 49152.0);
    }
}

// ----------------------------------------------------------------------------
// Entry point
// ----------------------------------------------------------------------------
extern "C" void kernel_launch(void* const* d_in, const int* in_sizes, int n_in,
                              void* d_out, int out_size) {
    const float* ei = (const float*)d_in[0];
    const float* ej = (const float*)d_in[1];
    (void)in_sizes; (void)n_in; (void)out_size;

    // 64KB dynamic smem for the GEMM kernel (not a stream op; capture-safe)
    cudaFuncSetAttribute(gemm_kernel, cudaFuncAttributeMaxDynamicSharedMemorySize,
                         SMEM_DYN);

    norm_kernel<<<TWO_N, 128>>>(ei, ej);
    pos_kernel<<<N_BATCH, 128>>>();
    gemm_kernel<<<NBLK_TRI, 256, SMEM_DYN>>>();
    fin_kernel<<<1, 256>>>((float*)d_out);
}

// round 3
// speedup vs baseline: 1.1582x; 1.1582x over previous
#include <cuda_runtime.h>
#include <cuda_bf16.h>
#include <cstdint>
#include <math.h>

// ----------------------------------------------------------------------------
// Problem constants
// ----------------------------------------------------------------------------
#define N_BATCH   4096
#define D_EMB     512
#define TWO_N     8192
#define LAMBDA    0.5f
#define TILE      128
#define NTILE     (TWO_N / TILE)                 // 64
#define NBLK_TRI  (NTILE * (NTILE + 1) / 2)      // 2080 lower-triangle tiles
#define KCHUNK    64                             // bf16 per K-chunk (128B rows)
#define NCHUNK    (D_EMB / KCHUNK)               // 8
#define STAGE_BYTES (TILE * 128)                 // 16384 per matrix per stage
#define NSTAGE    3
#define SMEM_DYN  (NSTAGE * 2 * STAGE_BYTES)     // 98304: 3 stages x (A,B)

// ----------------------------------------------------------------------------
// Device scratch (static — no allocations allowed)
// ----------------------------------------------------------------------------
__device__ __nv_bfloat16 g_reps[(size_t)TWO_N * D_EMB];   // 8 MB, L2-resident
__device__ float g_neg_part[NBLK_TRI];
__device__ float g_pos_part[N_BATCH];

// ----------------------------------------------------------------------------
// Helpers (arch-neutral PTX only: ldmatrix / mma.sync / cp.async)
// ----------------------------------------------------------------------------
__device__ __forceinline__ uint32_t smem_to_u32(const void* p) {
    uint32_t a;
    asm("{ .reg .u64 t; cvta.to.shared.u64 t, %1; cvt.u32.u64 %0, t; }" : "=r"(a) : "l"(p));
    return a;
}

__device__ __forceinline__ void ldsm_x4(uint32_t& r0, uint32_t& r1, uint32_t& r2,
                                        uint32_t& r3, uint32_t addr) {
    asm volatile("ldmatrix.sync.aligned.m8n8.x4.shared.b16 {%0,%1,%2,%3}, [%4];"
                 : "=r"(r0), "=r"(r1), "=r"(r2), "=r"(r3) : "r"(addr));
}

__device__ __forceinline__ void mma_16816(float* c, const uint32_t* a, uint32_t b0,
                                          uint32_t b1) {
    asm volatile(
        "mma.sync.aligned.m16n8k16.row.col.f32.bf16.bf16.f32 "
        "{%0,%1,%2,%3}, {%4,%5,%6,%7}, {%8,%9}, {%0,%1,%2,%3};"
        : "+f"(c[0]), "+f"(c[1]), "+f"(c[2]), "+f"(c[3])
        : "r"(a[0]), "r"(a[1]), "r"(a[2]), "r"(a[3]), "r"(b0), "r"(b1));
}

#define CP_ASYNC16(dst, src) \
    asm volatile("cp.async.cg.shared.global [%0], [%1], 16;" :: "r"(dst), "l"(src))
#define CP_COMMIT() asm volatile("cp.async.commit_group;" ::: "memory")
#define CP_WAIT(n)  asm volatile("cp.async.wait_group %0;" :: "n"(n) : "memory")

// SW128-style swizzle on 128B rows: 16B segment index XOR (row & 7) -> conflict-free
__device__ __forceinline__ uint32_t sw_off(int row, int seg) {
    return (uint32_t)(row * 128 + ((seg ^ (row & 7)) << 4));
}

// softplus(x) = x/2 + ln2 + v/2 - v^2/12 + v^3/45 - 17v^4/2520 + 31v^5/14175, v=(x/2)^2
// err < 1e-6 for |x| <= 1.2 (off-diag sims ~N(0,1/512): |x| <~ 0.9 incl. lambda shift)
__device__ __forceinline__ float softplus_poly(float x) {
    float v = 0.25f * x * x;
    float p = fmaf(v, 2.1869489e-3f, -6.7460317e-3f);
    p = fmaf(v, p, 2.2222222e-2f);
    p = fmaf(v, p, -8.3333333e-2f);
    p = fmaf(v, p, 0.5f);
    p = fmaf(v, p, 0.69314718056f);
    return fmaf(0.5f, x, p);
}

// ----------------------------------------------------------------------------
// Kernel 1 (fused): normalize pair k (rows k and k+N), write bf16 reps, and
// compute positives: softplus(lambda - z_i.z_j) using
//   z_i.z_j = (e_i.e_j) * rsqrt(|e_i|^2) * rsqrt(|e_j|^2)
// ----------------------------------------------------------------------------
__global__ __launch_bounds__(128) void normpos_kernel(const float* __restrict__ ei,
                                                      const float* __restrict__ ej) {
    int k = blockIdx.x;
    int tid = threadIdx.x;
    const float4 vi = ((const float4*)(ei + (size_t)k * D_EMB))[tid];
    const float4 vj = ((const float4*)(ej + (size_t)k * D_EMB))[tid];

    float ssi = vi.x * vi.x + vi.y * vi.y + vi.z * vi.z + vi.w * vi.w;
    float ssj = vj.x * vj.x + vj.y * vj.y + vj.z * vj.z + vj.w * vj.w;
    float dij = vi.x * vj.x + vi.y * vj.y + vi.z * vj.z + vi.w * vj.w;
#pragma unroll
    for (int o = 16; o > 0; o >>= 1) {
        ssi += __shfl_down_sync(0xffffffffu, ssi, o);
        ssj += __shfl_down_sync(0xffffffffu, ssj, o);
        dij += __shfl_down_sync(0xffffffffu, dij, o);
    }
    __shared__ float sr[3][4];
    if ((tid & 31) == 0) {
        sr[0][tid >> 5] = ssi; sr[1][tid >> 5] = ssj; sr[2][tid >> 5] = dij;
    }
    __syncthreads();
    float ti = sr[0][0] + sr[0][1] + sr[0][2] + sr[0][3];
    float tj = sr[1][0] + sr[1][1] + sr[1][2] + sr[1][3];
    float invi = rsqrtf(ti), invj = rsqrtf(tj);

    // write both bf16 rows (4 consecutive bf16 = 8B per thread, fully coalesced)
    __nv_bfloat16 bi[4] = {__float2bfloat16(vi.x * invi), __float2bfloat16(vi.y * invi),
                           __float2bfloat16(vi.z * invi), __float2bfloat16(vi.w * invi)};
    __nv_bfloat16 bj[4] = {__float2bfloat16(vj.x * invj), __float2bfloat16(vj.y * invj),
                           __float2bfloat16(vj.z * invj), __float2bfloat16(vj.w * invj)};
    ((uint2*)(g_reps + (size_t)k * D_EMB))[tid] = *(uint2*)bi;
    ((uint2*)(g_reps + (size_t)(k + N_BATCH) * D_EMB))[tid] = *(uint2*)bj;

    if (tid == 0) {
        float td = sr[2][0] + sr[2][1] + sr[2][2] + sr[2][3];
        g_pos_part[k] = log1pf(expf(LAMBDA - td * invi * invj));
    }
}

// ----------------------------------------------------------------------------
// Kernel 2: triangle-tiled HMMA GEMM with fused softplus-sum epilogue.
// One 256-thread CTA per lower-triangle 128x128 tile of sim = R R^T.
// 8 warps (4x2): warp computes a 32x64 strip via m16n8k16 bf16 mma.sync.
// 3-stage cp.async ring, ONE __syncthreads per K-chunk:
//   loads for chunk c+2 go into buf (c+2)%3 == (c-1)%3, which every warp
//   finished reading before the barrier at the top of chunk c.
// ----------------------------------------------------------------------------
__global__ __launch_bounds__(256, 2) void gemm_kernel() {
    extern __shared__ __align__(1024) uint8_t smem[];  // [stage][A|B][128][128B]
    __shared__ float s_red[8];

    // decode linear tile index -> (I, J) with I >= J
    int t = blockIdx.x;
    int I = (int)((sqrt(8.0 * (double)t + 1.0) - 1.0) * 0.5);
    while ((I + 1) * (I + 2) / 2 <= t) I++;
    while (I * (I + 1) / 2 > t) I--;
    int J = t - I * (I + 1) / 2;

    int tid = threadIdx.x, wid = tid >> 5, lane = tid & 31;
    int wm = wid & 3;        // row strip: wm*32
    int wn = wid >> 2;       // col strip: wn*64
    uint32_t sbase = smem_to_u32(smem);

    const __nv_bfloat16* repA = g_reps + (size_t)(I * TILE) * D_EMB;
    const __nv_bfloat16* repB = g_reps + (size_t)(J * TILE) * D_EMB;

    const int seg = tid & 7;        // 16B segment within 128B row
    const int rowbase = tid >> 3;   // 0..31

    auto load_stage = [&](int c, int stage) {
        uint32_t sA = sbase + stage * (2 * STAGE_BYTES);
        uint32_t sB = sA + STAGE_BYTES;
        const __nv_bfloat16* gA = repA + c * KCHUNK + seg * 8;
        const __nv_bfloat16* gB = repB + c * KCHUNK + seg * 8;
#pragma unroll
        for (int i = 0; i < 4; i++) {
            int row = rowbase + i * 32;
            uint32_t o = sw_off(row, seg);
            CP_ASYNC16(sA + o, gA + (size_t)row * D_EMB);
            CP_ASYNC16(sB + o, gB + (size_t)row * D_EMB);
        }
    };

    float acc[2][8][4];
#pragma unroll
    for (int mi = 0; mi < 2; mi++)
#pragma unroll
        for (int ni = 0; ni < 8; ni++)
#pragma unroll
            for (int p = 0; p < 4; p++) acc[mi][ni][p] = 0.f;

    const int lrow = lane & 15;      // row within 16-row group
    const int lhalf = lane >> 4;     // which 16B k-half

    load_stage(0, 0);
    CP_COMMIT();
    load_stage(1, 1);
    CP_COMMIT();

    for (int c = 0; c < NCHUNK; c++) {
        if (c < NCHUNK - 1) { CP_WAIT(1); } else { CP_WAIT(0); }
        __syncthreads();

        uint32_t sA = sbase + (c % NSTAGE) * (2 * STAGE_BYTES);
        uint32_t sB = sA + STAGE_BYTES;

#pragma unroll
        for (int k16 = 0; k16 < 4; k16++) {
            int kseg = k16 * 2 + lhalf;
            uint32_t a0[4], a1[4];
            {
                int r = wm * 32 + lrow;
                ldsm_x4(a0[0], a0[1], a0[2], a0[3], sA + sw_off(r, kseg));
                r += 16;
                ldsm_x4(a1[0], a1[1], a1[2], a1[3], sA + sw_off(r, kseg));
            }
            uint32_t br[4][4];
#pragma unroll
            for (int ng = 0; ng < 4; ng++) {
                int r = wn * 64 + ng * 16 + lrow;
                ldsm_x4(br[ng][0], br[ng][1], br[ng][2], br[ng][3],
                        sB + sw_off(r, kseg));
            }
#pragma unroll
            for (int ni = 0; ni < 8; ni++) {
                int ng = ni >> 1, hi = ni & 1;
                mma_16816(acc[0][ni], a0, br[ng][hi], br[ng][hi + 2]);
                mma_16816(acc[1][ni], a1, br[ng][hi], br[ng][hi + 2]);
            }
        }

        // prefetch chunk c+2 into ring slot (c+2)%3 (safe: last read at chunk c-1,
        // all warps passed this chunk's barrier after finishing c-1)
        if (c + 2 < NCHUNK) {
            load_stage(c + 2, (c + 2) % NSTAGE);
            CP_COMMIT();
        }
    }

    // Fused epilogue: softplus(sim - lambda), mask true diagonal, x2 off-diag tiles
    bool diag = (I == J);
    int row0 = I * TILE + wm * 32 + (lane >> 2);
    int col0 = J * TILE + wn * 64 + (lane & 3) * 2;
    float asum = 0.f;
#pragma unroll
    for (int mi = 0; mi < 2; mi++) {
#pragma unroll
        for (int ni = 0; ni < 8; ni++) {
#pragma unroll
            for (int p = 0; p < 4; p++) {
                int gr = row0 + mi * 16 + ((p >> 1) << 3);
                int gc = col0 + ni * 8 + (p & 1);
                float g = softplus_poly(acc[mi][ni][p] - LAMBDA);
                if (!diag || gr != gc) asum += g;
            }
        }
    }
    if (!diag) asum *= 2.f;

#pragma unroll
    for (int o = 16; o > 0; o >>= 1) asum += __shfl_down_sync(0xffffffffu, asum, o);
    if (lane == 0) s_red[wid] = asum;
    __syncthreads();
    if (tid == 0) {
        float s = 0.f;
#pragma unroll
        for (int w = 0; w < 8; w++) s += s_red[w];
        g_neg_part[t] = s;
    }
}

// ----------------------------------------------------------------------------
// Kernel 3: deterministic final reduction (1024 threads, vectorized, MLP-rich)
// ----------------------------------------------------------------------------
__global__ __launch_bounds__(1024) void fin_kernel(float* __restrict__ out) {
    int tid = threadIdx.x;
    double s = 0.0;
    // negatives: 2080 floats = 520 float4
    if (tid < NBLK_TRI / 4) {
        float4 v = ((const float4*)g_neg_part)[tid];
        s += ((double)v.x + (double)v.y + (double)v.z + (double)v.w) / 49152.0;
    }
    // positives: 4096 floats = 1024 float4 (exactly one per thread)
    {
        float4 v = ((const float4*)g_pos_part)[tid];
        s += ((double)v.x + (double)v.y + (double)v.z + (double)v.w) / 4096.0;
    }
#pragma unroll
    for (int o = 16; o > 0; o >>= 1) s += __shfl_down_sync(0xffffffffu, s, o);
    __shared__ double sh[32];
    if ((tid & 31) == 0) sh[tid >> 5] = s;
    __syncthreads();
    if (tid == 0) {
        double tot = 0.0;
#pragma unroll
        for (int i = 0; i < 32; i++) tot += sh[i];
        out[0] = (float)tot;
    }
}

// ----------------------------------------------------------------------------
// Entry point
// ----------------------------------------------------------------------------
extern "C" void kernel_launch(void* const* d_in, const int* in_sizes, int n_in,
                              void* d_out, int out_size) {
    const float* ei = (const float*)d_in[0];
    const float* ej = (const float*)d_in[1];
    (void)in_sizes; (void)n_in; (void)out_size;

    cudaFuncSetAttribute(gemm_kernel, cudaFuncAttributeMaxDynamicSharedMemorySize,
                         SMEM_DYN);

    normpos_kernel<<<N_BATCH, 128>>>(ei, ej);
    gemm_kernel<<<NBLK_TRI, 256, SMEM_DYN>>>();
    fin_kernel<<<1, 1024>>>((float*)d_out);
}